// round 4
// baseline (speedup 1.0000x reference)
#include <cuda_runtime.h>

#define NN   50000
#define NE   800000
#define FDIM 128

// ---- scratch (device globals; no allocation allowed) ----
__device__ int   g_deg[NN];
__device__ int   g_fill[NN];
__device__ int   g_rowptr[NN + 1];
__device__ int   g_col[NE];
__device__ float g_invdeg[NN];
__device__ float g_agg[NN * FDIM];
__device__ float g_h[NN * FDIM];

// ---------------------------------------------------------------------------
__global__ void k_zero() {
    int i = blockIdx.x * blockDim.x + threadIdx.x;
    if (i < NN) { g_deg[i] = 0; g_fill[i] = 0; }
}

__global__ void k_hist(const int* __restrict__ dst) {
    int e = blockIdx.x * blockDim.x + threadIdx.x;
    if (e < NE) atomicAdd(&g_deg[dst[e]], 1);
}

// single-block exclusive scan of g_deg -> g_rowptr, plus inv_deg
__global__ void k_scan() {
    const int T = 1024;
    const int CH = (NN + T - 1) / T;  // 49
    __shared__ int ssum[T];
    int t = threadIdx.x;
    int base = t * CH;
    int s = 0;
    for (int j = 0; j < CH; j++) {
        int idx = base + j;
        if (idx < NN) s += g_deg[idx];
    }
    ssum[t] = s;
    __syncthreads();
    // Hillis-Steele inclusive scan over 1024 partial sums
    for (int off = 1; off < T; off <<= 1) {
        int v = 0;
        if (t >= off) v = ssum[t - off];
        __syncthreads();
        if (t >= off) ssum[t] += v;
        __syncthreads();
    }
    int run = (t > 0) ? ssum[t - 1] : 0;
    for (int j = 0; j < CH; j++) {
        int idx = base + j;
        if (idx < NN) {
            g_rowptr[idx] = run;
            int d = g_deg[idx];
            g_invdeg[idx] = (d > 0) ? (1.0f / (float)d) : 0.0f;
            run += d;
        }
    }
    if (t == T - 1) g_rowptr[NN] = run;
}

__global__ void k_fill(const int* __restrict__ src, const int* __restrict__ dst) {
    int e = blockIdx.x * blockDim.x + threadIdx.x;
    if (e < NE) {
        int d = dst[e];
        int pos = g_rowptr[d] + atomicAdd(&g_fill[d], 1);
        g_col[pos] = src[e];
    }
}

// ---------------------------------------------------------------------------
// mean-aggregate into g_agg: one warp per node, lane l covers feats [4l,4l+4)
// feat == nullptr  ->  read from g_h
__global__ __launch_bounds__(256) void k_agg(const float* __restrict__ feat) {
    int warp = (blockIdx.x * blockDim.x + threadIdx.x) >> 5;
    int lane = threadIdx.x & 31;
    if (warp >= NN) return;
    const float4* fv = feat ? (const float4*)feat : (const float4*)g_h;
    int beg = g_rowptr[warp], end = g_rowptr[warp + 1];
    float4 a0 = make_float4(0.f, 0.f, 0.f, 0.f);
    float4 a1 = make_float4(0.f, 0.f, 0.f, 0.f);
    int e = beg;
    for (; e + 1 < end; e += 2) {
        int s0 = g_col[e];
        int s1 = g_col[e + 1];
        float4 v0 = __ldg(fv + s0 * 32 + lane);
        float4 v1 = __ldg(fv + s1 * 32 + lane);
        a0.x += v0.x; a0.y += v0.y; a0.z += v0.z; a0.w += v0.w;
        a1.x += v1.x; a1.y += v1.y; a1.z += v1.z; a1.w += v1.w;
    }
    if (e < end) {
        int s0 = g_col[e];
        float4 v0 = __ldg(fv + s0 * 32 + lane);
        a0.x += v0.x; a0.y += v0.y; a0.z += v0.z; a0.w += v0.w;
    }
    float inv = g_invdeg[warp];
    float4 r;
    r.x = (a0.x + a1.x) * inv;
    r.y = (a0.y + a1.y) * inv;
    r.z = (a0.z + a1.z) * inv;
    r.w = (a0.w + a1.w) * inv;
    ((float4*)g_agg)[warp * 32 + lane] = r;
}

// ---------------------------------------------------------------------------
// fused dual SGEMM: out = g_agg@W1 + A2@W2 + bias  (optional relu)
// A2 == nullptr -> g_h ; outp == nullptr -> g_h
// A: [NN,128] row-major; W1/W2: [128,128] row-major; out: [NN,128]
#define BM 64
#define BN 128
#define BKK 16
__global__ __launch_bounds__(256) void k_gemm(
    const float* __restrict__ A2_in,
    const float* __restrict__ W1, const float* __restrict__ W2,
    const float* __restrict__ bias, float* __restrict__ out_in, int do_relu)
{
    __shared__ float As[BKK][BM];
    __shared__ float Bs[BKK][BN];
    const float* A2 = A2_in ? A2_in : (const float*)g_h;
    float* outp = out_in ? out_in : (float*)g_h;

    int tid = threadIdx.x;
    int row0 = blockIdx.x * BM;
    int tr = tid >> 4;   // 0..15 -> rows tr*4..tr*4+3
    int tc = tid & 15;   // 0..15 -> cols tc*8..tc*8+7
    float acc[4][8];
#pragma unroll
    for (int i = 0; i < 4; i++)
#pragma unroll
        for (int j = 0; j < 8; j++) acc[i][j] = 0.f;

    int aRow  = tid >> 2;  // 0..63
    int aCol4 = tid & 3;   // float4 index within 16-wide k slab
    int bRow  = tid >> 5;  // 0..7 (also loads bRow+8)
    int bCol4 = tid & 31;  // float4 index across 128 cols

#pragma unroll
    for (int half = 0; half < 2; half++) {
        const float* A = half ? A2 : (const float*)g_agg;
        const float* W = half ? W2 : W1;
        for (int kb = 0; kb < FDIM; kb += BKK) {
            int gr = row0 + aRow;
            float4 av = make_float4(0.f, 0.f, 0.f, 0.f);
            if (gr < NN)
                av = __ldg((const float4*)(A + gr * FDIM + kb) + aCol4);
            As[aCol4 * 4 + 0][aRow] = av.x;
            As[aCol4 * 4 + 1][aRow] = av.y;
            As[aCol4 * 4 + 2][aRow] = av.z;
            As[aCol4 * 4 + 3][aRow] = av.w;

            float4 bv0 = __ldg((const float4*)(W + (kb + bRow) * FDIM) + bCol4);
            float4 bv1 = __ldg((const float4*)(W + (kb + bRow + 8) * FDIM) + bCol4);
            ((float4*)Bs[bRow])[bCol4]     = bv0;
            ((float4*)Bs[bRow + 8])[bCol4] = bv1;
            __syncthreads();

#pragma unroll
            for (int k = 0; k < BKK; k++) {
                float rm[4];
#pragma unroll
                for (int i = 0; i < 4; i++) rm[i] = As[k][tr * 4 + i];
                float4 n0 = *((float4*)&Bs[k][tc * 8]);
                float4 n1 = *((float4*)&Bs[k][tc * 8 + 4]);
                float rn[8] = {n0.x, n0.y, n0.z, n0.w, n1.x, n1.y, n1.z, n1.w};
#pragma unroll
                for (int i = 0; i < 4; i++)
#pragma unroll
                    for (int j = 0; j < 8; j++)
                        acc[i][j] = fmaf(rm[i], rn[j], acc[i][j]);
            }
            __syncthreads();
        }
    }

    float4 b0 = __ldg((const float4*)bias + tc * 2);
    float4 b1 = __ldg((const float4*)bias + tc * 2 + 1);
#pragma unroll
    for (int i = 0; i < 4; i++) {
        int gr = row0 + tr * 4 + i;
        if (gr < NN) {
            float4 v0, v1;
            v0.x = acc[i][0] + b0.x; v0.y = acc[i][1] + b0.y;
            v0.z = acc[i][2] + b0.z; v0.w = acc[i][3] + b0.w;
            v1.x = acc[i][4] + b1.x; v1.y = acc[i][5] + b1.y;
            v1.z = acc[i][6] + b1.z; v1.w = acc[i][7] + b1.w;
            if (do_relu) {
                v0.x = fmaxf(v0.x, 0.f); v0.y = fmaxf(v0.y, 0.f);
                v0.z = fmaxf(v0.z, 0.f); v0.w = fmaxf(v0.w, 0.f);
                v1.x = fmaxf(v1.x, 0.f); v1.y = fmaxf(v1.y, 0.f);
                v1.z = fmaxf(v1.z, 0.f); v1.w = fmaxf(v1.w, 0.f);
            }
            float4* dst = (float4*)(outp + gr * FDIM + tc * 8);
            dst[0] = v0;
            dst[1] = v1;
        }
    }
}

// ---------------------------------------------------------------------------
// final layer (C=4): out[i,c] = g_agg[i]@Wl2[:,c] + h2[i]@Wr2[:,c] + b[c]
// one warp per node; result written twice (out, out) per reference tuple
__global__ __launch_bounds__(256) void k_out(
    const float* __restrict__ h2,
    const float* __restrict__ Wl, const float* __restrict__ Wr,
    const float* __restrict__ b, float* __restrict__ outp)
{
    __shared__ float sWl[FDIM * 4];
    __shared__ float sWr[FDIM * 4];
    __shared__ float sb[4];
    int tid = threadIdx.x;
    for (int i = tid; i < FDIM * 4; i += blockDim.x) {
        sWl[i] = Wl[i];
        sWr[i] = Wr[i];
    }
    if (tid < 4) sb[tid] = b[tid];
    __syncthreads();

    int warp = (blockIdx.x * blockDim.x + tid) >> 5;
    int lane = tid & 31;
    if (warp >= NN) return;

    float4 m = ((const float4*)g_agg)[warp * 32 + lane];
    float4 x = ((const float4*)h2)[warp * 32 + lane];
    float mv[4] = {m.x, m.y, m.z, m.w};
    float xv[4] = {x.x, x.y, x.z, x.w};
    float acc[4] = {0.f, 0.f, 0.f, 0.f};
#pragma unroll
    for (int j = 0; j < 4; j++) {
        int f = 4 * lane + j;
#pragma unroll
        for (int c = 0; c < 4; c++)
            acc[c] += mv[j] * sWl[f * 4 + c] + xv[j] * sWr[f * 4 + c];
    }
#pragma unroll
    for (int off = 16; off > 0; off >>= 1) {
#pragma unroll
        for (int c = 0; c < 4; c++)
            acc[c] += __shfl_xor_sync(0xffffffffu, acc[c], off);
    }
    if (lane == 0) {
#pragma unroll
        for (int c = 0; c < 4; c++) {
            float v = acc[c] + sb[c];
            outp[warp * 4 + c] = v;                  // out  (first copy)
            outp[NN * 4 + warp * 4 + c] = v;         // out  (second copy)
        }
    }
}

// ---------------------------------------------------------------------------
extern "C" void kernel_launch(void* const* d_in, const int* in_sizes, int n_in,
                              void* d_out, int out_size) {
    const float* x   = (const float*)d_in[0];
    const int*   ei  = (const int*)d_in[1];
    const int*   src = ei;
    const int*   dst = ei + NE;
    const float* Wl0 = (const float*)d_in[2];
    const float* bl0 = (const float*)d_in[3];
    const float* Wr0 = (const float*)d_in[4];
    const float* Wl1 = (const float*)d_in[5];
    const float* bl1 = (const float*)d_in[6];
    const float* Wr1 = (const float*)d_in[7];
    const float* Wl2 = (const float*)d_in[8];
    const float* bl2 = (const float*)d_in[9];
    const float* Wr2 = (const float*)d_in[10];

    float* outp = (float*)d_out;
    float* h2   = outp + 2 * NN * 4;   // h2 lives directly in d_out

    // CSR build (by destination)
    k_zero<<<(NN + 255) / 256, 256>>>();
    k_hist<<<(NE + 255) / 256, 256>>>(dst);
    k_scan<<<1, 1024>>>();
    k_fill<<<(NE + 255) / 256, 256>>>(src, dst);

    const int aggBlocks  = (NN + 7) / 8;      // 8 warps / block
    const int gemmBlocks = (NN + BM - 1) / BM;

    // layer 0: g_h = relu(mean(x)@Wl0 + x@Wr0 + bl0)
    k_agg<<<aggBlocks, 256>>>(x);
    k_gemm<<<gemmBlocks, 256>>>(x, Wl0, Wr0, bl0, nullptr, 1);

    // layer 1: h2 = mean(g_h)@Wl1 + g_h@Wr1 + bl1   (written straight into d_out)
    k_agg<<<aggBlocks, 256>>>(nullptr);
    k_gemm<<<gemmBlocks, 256>>>(nullptr, Wl1, Wr1, bl1, h2, 0);

    // layer 2: out = mean(h2)@Wl2 + h2@Wr2 + bl2  (C=4), duplicated
    k_agg<<<aggBlocks, 256>>>(h2);
    k_out<<<aggBlocks, 256>>>(h2, Wl2, Wr2, bl2, outp);
}

// round 7
// speedup vs baseline: 1.6477x; 1.6477x over previous
#include <cuda_runtime.h>
#include <cstdint>

#define NN   50000
#define NE   800000
#define FDIM 128

// ---- scratch (device globals; no allocation allowed) ----
__device__ int   g_deg[NN];
__device__ int   g_fill[NN];
__device__ int   g_rowptr[NN + 1];
__device__ int   g_col[NE];
__device__ float g_invdeg[NN];
__device__ float g_agg[NN * FDIM];
__device__ float g_h[NN * FDIM];
__device__ float g_Wt[FDIM * 2 * FDIM];   // [n][k], k = 0..255 (Wl | Wr)

// ===========================================================================
// CSR build
// ===========================================================================
__global__ void k_zero() {
    int i = blockIdx.x * blockDim.x + threadIdx.x;
    if (i < NN) { g_deg[i] = 0; g_fill[i] = 0; }
}

__global__ void k_hist(const int* __restrict__ dst) {
    int e = blockIdx.x * blockDim.x + threadIdx.x;
    if (e < NE) atomicAdd(&g_deg[dst[e]], 1);
}

__global__ void k_scan() {
    const int T = 1024;
    const int CH = (NN + T - 1) / T;
    __shared__ int ssum[T];
    int t = threadIdx.x;
    int base = t * CH;
    int s = 0;
    for (int j = 0; j < CH; j++) {
        int idx = base + j;
        if (idx < NN) s += g_deg[idx];
    }
    ssum[t] = s;
    __syncthreads();
    for (int off = 1; off < T; off <<= 1) {
        int v = 0;
        if (t >= off) v = ssum[t - off];
        __syncthreads();
        if (t >= off) ssum[t] += v;
        __syncthreads();
    }
    int run = (t > 0) ? ssum[t - 1] : 0;
    for (int j = 0; j < CH; j++) {
        int idx = base + j;
        if (idx < NN) {
            g_rowptr[idx] = run;
            int d = g_deg[idx];
            g_invdeg[idx] = (d > 0) ? (1.0f / (float)d) : 0.0f;
            run += d;
        }
    }
    if (t == T - 1) g_rowptr[NN] = run;
}

__global__ void k_fill(const int* __restrict__ src, const int* __restrict__ dst) {
    int e = blockIdx.x * blockDim.x + threadIdx.x;
    if (e < NE) {
        int d = dst[e];
        int pos = g_rowptr[d] + atomicAdd(&g_fill[d], 1);
        g_col[pos] = src[e];
    }
}

// ===========================================================================
// transpose weights into g_Wt:  g_Wt[n*256 + k] = W1[k][n] ; +128 -> W2
// ===========================================================================
__global__ void k_transW(const float* __restrict__ W1, const float* __restrict__ W2) {
    int i = blockIdx.x * blockDim.x + threadIdx.x;
    if (i < FDIM * FDIM) {
        int k = i >> 7, n = i & 127;
        g_Wt[n * 256 + k]       = W1[i];
        g_Wt[n * 256 + 128 + k] = W2[i];
    }
}

// ===========================================================================
// mean-aggregate into g_agg (one warp per node; feat==nullptr -> g_h)
// ===========================================================================
__global__ __launch_bounds__(256) void k_agg(const float* __restrict__ feat) {
    int warp = (blockIdx.x * blockDim.x + threadIdx.x) >> 5;
    int lane = threadIdx.x & 31;
    if (warp >= NN) return;
    const float4* fv = feat ? (const float4*)feat : (const float4*)g_h;
    int beg = g_rowptr[warp], end = g_rowptr[warp + 1];
    float4 a0 = make_float4(0.f, 0.f, 0.f, 0.f);
    float4 a1 = make_float4(0.f, 0.f, 0.f, 0.f);
    int e = beg;
    for (; e + 1 < end; e += 2) {
        int s0 = g_col[e];
        int s1 = g_col[e + 1];
        float4 v0 = __ldg(fv + s0 * 32 + lane);
        float4 v1 = __ldg(fv + s1 * 32 + lane);
        a0.x += v0.x; a0.y += v0.y; a0.z += v0.z; a0.w += v0.w;
        a1.x += v1.x; a1.y += v1.y; a1.z += v1.z; a1.w += v1.w;
    }
    if (e < end) {
        int s0 = g_col[e];
        float4 v0 = __ldg(fv + s0 * 32 + lane);
        a0.x += v0.x; a0.y += v0.y; a0.z += v0.z; a0.w += v0.w;
    }
    float inv = g_invdeg[warp];
    float4 r;
    r.x = (a0.x + a1.x) * inv;
    r.y = (a0.y + a1.y) * inv;
    r.z = (a0.z + a1.z) * inv;
    r.w = (a0.w + a1.w) * inv;
    ((float4*)g_agg)[warp * 32 + lane] = r;
}

// ===========================================================================
// tf32 mma.sync fused dual GEMM:
//   out = g_agg @ Wl^T + A2 @ Wr^T + bias   (A2==nullptr -> g_h, out==nullptr -> g_h)
// CTA tile 128x128, 8 warps each 64x32, BK=32 chunks (4 from g_agg, 4 from A2)
// ===========================================================================
__device__ __forceinline__ uint32_t f2tf32(float f) {
    uint32_t u;
    asm("cvt.rna.tf32.f32 %0, %1;" : "=r"(u) : "f"(f));
    return u;
}

__device__ __forceinline__ void mma_tf32(float* d, const uint32_t* a, const uint32_t* b) {
    asm volatile(
        "mma.sync.aligned.m16n8k8.row.col.f32.tf32.tf32.f32 "
        "{%0,%1,%2,%3}, {%4,%5,%6,%7}, {%8,%9}, {%0,%1,%2,%3};"
        : "+f"(d[0]), "+f"(d[1]), "+f"(d[2]), "+f"(d[3])
        : "r"(a[0]), "r"(a[1]), "r"(a[2]), "r"(a[3]), "r"(b[0]), "r"(b[1]));
}

#define SSTR 36   // smem row stride (floats): conflict-free (36 % 32 == 4), 16B-aligned

__global__ __launch_bounds__(256) void k_gemm(
    const float* __restrict__ A2_in, const float* __restrict__ bias,
    float* __restrict__ out_in, int do_relu)
{
    __shared__ uint32_t sA[128 * SSTR];
    __shared__ uint32_t sB[128 * SSTR];

    const float* A1 = (const float*)g_agg;
    const float* A2 = A2_in ? A2_in : (const float*)g_h;
    float* outp = out_in ? out_in : (float*)g_h;

    int tid  = threadIdx.x;
    int wid  = tid >> 5;
    int lane = tid & 31;
    int row0 = blockIdx.x * 128;

    int wr = (wid & 1) * 64;    // warp row base within tile
    int wc = (wid >> 1) * 32;   // warp col base within tile
    int qr = lane >> 2;         // 0..7
    int qc = lane & 3;          // 0..3

    float acc[4][4][4];
#pragma unroll
    for (int mi = 0; mi < 4; mi++)
#pragma unroll
        for (int ni = 0; ni < 4; ni++)
#pragma unroll
            for (int r = 0; r < 4; r++) acc[mi][ni][r] = 0.f;

    for (int c = 0; c < 8; c++) {
        const float* Asrc = (c < 4) ? A1 : A2;
        int cb = (c & 3) * 32;

        // stage A chunk (128 rows x 32 k) and B chunk (128 n x 32 k), tf32-converted
#pragma unroll
        for (int j = 0; j < 4; j++) {
            int i = tid + j * 256;            // 0..1023
            int r = i >> 3, q = i & 7;        // row, float4-col
            int gr = row0 + r;
            float4 v = make_float4(0.f, 0.f, 0.f, 0.f);
            if (gr < NN)
                v = __ldg((const float4*)(Asrc + gr * FDIM + cb) + q);
            uint32_t* dstp = &sA[r * SSTR + q * 4];
            dstp[0] = f2tf32(v.x); dstp[1] = f2tf32(v.y);
            dstp[2] = f2tf32(v.z); dstp[3] = f2tf32(v.w);

            float4 w = __ldg((const float4*)(g_Wt + r * 256 + c * 32) + q);
            uint32_t* dstw = &sB[r * SSTR + q * 4];
            dstw[0] = f2tf32(w.x); dstw[1] = f2tf32(w.y);
            dstw[2] = f2tf32(w.z); dstw[3] = f2tf32(w.w);
        }
        __syncthreads();

#pragma unroll
        for (int ks = 0; ks < 4; ks++) {
            int k0 = ks * 8;
            uint32_t a[4][4];
#pragma unroll
            for (int mi = 0; mi < 4; mi++) {
                int r0 = wr + mi * 16;
                a[mi][0] = sA[(r0 + qr)     * SSTR + k0 + qc];
                a[mi][1] = sA[(r0 + qr + 8) * SSTR + k0 + qc];
                a[mi][2] = sA[(r0 + qr)     * SSTR + k0 + qc + 4];
                a[mi][3] = sA[(r0 + qr + 8) * SSTR + k0 + qc + 4];
            }
            uint32_t b[4][2];
#pragma unroll
            for (int ni = 0; ni < 4; ni++) {
                int n0 = wc + ni * 8;
                b[ni][0] = sB[(n0 + qr) * SSTR + k0 + qc];
                b[ni][1] = sB[(n0 + qr) * SSTR + k0 + qc + 4];
            }
#pragma unroll
            for (int mi = 0; mi < 4; mi++)
#pragma unroll
                for (int ni = 0; ni < 4; ni++)
                    mma_tf32(acc[mi][ni], a[mi], b[ni]);
        }
        __syncthreads();
    }

    // epilogue: c0,c1 at (row, col..col+1); c2,c3 at (row+8, ...)
#pragma unroll
    for (int mi = 0; mi < 4; mi++) {
        int rA = row0 + wr + mi * 16 + qr;
        int rB = rA + 8;
#pragma unroll
        for (int ni = 0; ni < 4; ni++) {
            int col = wc + ni * 8 + qc * 2;
            float b0 = __ldg(bias + col);
            float b1 = __ldg(bias + col + 1);
            float v0 = acc[mi][ni][0] + b0;
            float v1 = acc[mi][ni][1] + b1;
            float v2 = acc[mi][ni][2] + b0;
            float v3 = acc[mi][ni][3] + b1;
            if (do_relu) {
                v0 = fmaxf(v0, 0.f); v1 = fmaxf(v1, 0.f);
                v2 = fmaxf(v2, 0.f); v3 = fmaxf(v3, 0.f);
            }
            if (rA < NN) *(float2*)(outp + (size_t)rA * FDIM + col) = make_float2(v0, v1);
            if (rB < NN) *(float2*)(outp + (size_t)rB * FDIM + col) = make_float2(v2, v3);
        }
    }
}

// ===========================================================================
// final layer (C=4): out[i,c] = g_agg[i]@Wl2[:,c] + h2[i]@Wr2[:,c] + b[c]
// ===========================================================================
__global__ __launch_bounds__(256) void k_out(
    const float* __restrict__ h2,
    const float* __restrict__ Wl, const float* __restrict__ Wr,
    const float* __restrict__ b, float* __restrict__ outp)
{
    __shared__ float sWl[FDIM * 4];
    __shared__ float sWr[FDIM * 4];
    __shared__ float sb[4];
    int tid = threadIdx.x;
    for (int i = tid; i < FDIM * 4; i += blockDim.x) {
        sWl[i] = Wl[i];
        sWr[i] = Wr[i];
    }
    if (tid < 4) sb[tid] = b[tid];
    __syncthreads();

    int warp = (blockIdx.x * blockDim.x + tid) >> 5;
    int lane = tid & 31;
    if (warp >= NN) return;

    float4 m = ((const float4*)g_agg)[warp * 32 + lane];
    float4 x = ((const float4*)h2)[warp * 32 + lane];
    float mv[4] = {m.x, m.y, m.z, m.w};
    float xv[4] = {x.x, x.y, x.z, x.w};
    float acc[4] = {0.f, 0.f, 0.f, 0.f};
#pragma unroll
    for (int j = 0; j < 4; j++) {
        int f = 4 * lane + j;
#pragma unroll
        for (int c = 0; c < 4; c++)
            acc[c] += mv[j] * sWl[f * 4 + c] + xv[j] * sWr[f * 4 + c];
    }
#pragma unroll
    for (int off = 16; off > 0; off >>= 1) {
#pragma unroll
        for (int c = 0; c < 4; c++)
            acc[c] += __shfl_xor_sync(0xffffffffu, acc[c], off);
    }
    if (lane == 0) {
#pragma unroll
        for (int c = 0; c < 4; c++) {
            float v = acc[c] + sb[c];
            outp[warp * 4 + c] = v;
            outp[NN * 4 + warp * 4 + c] = v;
        }
    }
}

// ===========================================================================
extern "C" void kernel_launch(void* const* d_in, const int* in_sizes, int n_in,
                              void* d_out, int out_size) {
    const float* x   = (const float*)d_in[0];
    const int*   ei  = (const int*)d_in[1];
    const int*   src = ei;
    const int*   dst = ei + NE;
    const float* Wl0 = (const float*)d_in[2];
    const float* bl0 = (const float*)d_in[3];
    const float* Wr0 = (const float*)d_in[4];
    const float* Wl1 = (const float*)d_in[5];
    const float* bl1 = (const float*)d_in[6];
    const float* Wr1 = (const float*)d_in[7];
    const float* Wl2 = (const float*)d_in[8];
    const float* bl2 = (const float*)d_in[9];
    const float* Wr2 = (const float*)d_in[10];

    float* outp = (float*)d_out;
    float* h2   = outp + 2 * NN * 4;   // h2 lives directly in d_out

    // CSR build (by destination)
    k_zero<<<(NN + 255) / 256, 256>>>();
    k_hist<<<(NE + 255) / 256, 256>>>(dst);
    k_scan<<<1, 1024>>>();
    k_fill<<<(NE + 255) / 256, 256>>>(src, dst);

    const int aggBlocks  = (NN + 7) / 8;
    const int gemmBlocks = (NN + 127) / 128;   // 391
    const int twBlocks   = (FDIM * FDIM + 255) / 256;

    // layer 0: g_h = relu(mean(x)@Wl0 + x@Wr0 + bl0)
    k_transW<<<twBlocks, 256>>>(Wl0, Wr0);
    k_agg<<<aggBlocks, 256>>>(x);
    k_gemm<<<gemmBlocks, 256>>>(x, bl0, nullptr, 1);

    // layer 1: h2 = mean(g_h)@Wl1 + g_h@Wr1 + bl1
    k_transW<<<twBlocks, 256>>>(Wl1, Wr1);
    k_agg<<<aggBlocks, 256>>>(nullptr);
    k_gemm<<<gemmBlocks, 256>>>(nullptr, bl1, h2, 0);

    // layer 2: out = mean(h2)@Wl2 + h2@Wr2 + bl2  (C=4), duplicated
    k_agg<<<aggBlocks, 256>>>(h2);
    k_out<<<aggBlocks, 256>>>(h2, Wl2, Wr2, bl2, outp);
}